// round 12
// baseline (speedup 1.0000x reference)
#include <cuda_runtime.h>
#include <math.h>

// Segment sums + completion counter, zero-initialized at module load; block 0
// re-zeroes them each run so graph replays are deterministic.
__device__ float g_pos_sum[8192];
__device__ float g_neg_sum[8192];
__device__ unsigned int g_ctr;

// ---------------------------------------------------------------------------
// Persistent kernel.
//   Streaming: grid-stride warp-per-row (identical hot path to the 119.3us
//   kernel: 16 LDG.128 in flight, shuffle reduce, relaxed SPREAD segment
//   atomics -- measured free). Full occupancy: 1184 blocks x 8 warps = 64
//   warps/SM, fixing R11's 41%-occ failure.
//   Tail: ONE syncthreads + gpu fence + counter bump per resident block,
//   fired only after that block's streaming is done (1184 fences post-stream,
//   vs R4's 12800 mid-stream -- the difference that killed R4).
//   Block 0 warp 0 spins on the counter, then finalizes and resets scratch.
// ---------------------------------------------------------------------------
__global__ void __launch_bounds__(256) contrastive_persistent_kernel(
    const float* __restrict__ q_pos, const float* __restrict__ i_pos,
    const float* __restrict__ q_neg, const float* __restrict__ i_neg,
    float* __restrict__ out, int pos_rows, int total_rows, int n_items)
{
    const int lane = threadIdx.x & 31;
    const int gwarp = (blockIdx.x * blockDim.x + threadIdx.x) >> 5;
    const int nwarps = (gridDim.x * blockDim.x) >> 5;

    // ---- Streaming phase: grid-stride over rows, no sync anywhere ----
    for (int w = gwarp; w < total_rows; w += nwarps) {
        const float4* __restrict__ a4;
        const float4* __restrict__ b4;
        float* __restrict__ dst;
        if (w < pos_rows) {
            a4 = reinterpret_cast<const float4*>(q_pos) + (size_t)w * 256;
            b4 = reinterpret_cast<const float4*>(i_pos) + (size_t)w * 256;
            dst = &g_pos_sum[w >> 1];                  // 2 pos rows per item
        } else {
            const int r = w - pos_rows;
            a4 = reinterpret_cast<const float4*>(q_neg) + (size_t)r * 256;
            b4 = reinterpret_cast<const float4*>(i_neg) + (size_t)r * 256;
            dst = &g_neg_sum[r / 23];                  // 23 neg rows per item
        }

        float dot = 0.0f, na2 = 0.0f, nb2 = 0.0f;
#pragma unroll
        for (int i = 0; i < 8; i++) {
            float4 va = __ldg(a4 + lane + i * 32);
            float4 vb = __ldg(b4 + lane + i * 32);
            dot = fmaf(va.x, vb.x, dot); na2 = fmaf(va.x, va.x, na2); nb2 = fmaf(vb.x, vb.x, nb2);
            dot = fmaf(va.y, vb.y, dot); na2 = fmaf(va.y, va.y, na2); nb2 = fmaf(vb.y, vb.y, nb2);
            dot = fmaf(va.z, vb.z, dot); na2 = fmaf(va.z, va.z, na2); nb2 = fmaf(vb.z, vb.z, nb2);
            dot = fmaf(va.w, vb.w, dot); na2 = fmaf(va.w, va.w, na2); nb2 = fmaf(vb.w, vb.w, nb2);
        }
#pragma unroll
        for (int off = 16; off > 0; off >>= 1) {
            dot += __shfl_xor_sync(0xffffffffu, dot, off);
            na2 += __shfl_xor_sync(0xffffffffu, na2, off);
            nb2 += __shfl_xor_sync(0xffffffffu, nb2, off);
        }
        if (lane == 0) {
            float denom = fmaxf(sqrtf(na2) * sqrtf(nb2), 1e-8f);
            atomicAdd(dst, expf(dot / denom));         // relaxed, spread: free
        }
    }

    // ---- Tail handshake: once per resident block, after streaming ----
    __syncthreads();
    if (threadIdx.x == 0) {
        __threadfence();                    // publish this block's atomics
        atomicAdd(&g_ctr, 1u);              // 1184 total, post-stream only
    }

    // ---- Finalizer: block 0, warp 0 ----
    if (blockIdx.x != 0 || threadIdx.x >= 32) return;

    if (lane == 0) {
        unsigned int c;
        do {
            asm volatile("ld.acquire.gpu.global.u32 %0, [%1];"
                         : "=r"(c) : "l"(&g_ctr) : "memory");
            if (c < gridDim.x) __nanosleep(128);
        } while (c < gridDim.x);
    }
    __syncwarp();

    const float4* p4 = reinterpret_cast<const float4*>(g_pos_sum);
    const float4* n4 = reinterpret_cast<const float4*>(g_neg_sum);
    float4* p4w = reinterpret_cast<float4*>(g_pos_sum);
    float4* n4w = reinterpret_cast<float4*>(g_neg_sum);
    const float4 z4 = make_float4(0.f, 0.f, 0.f, 0.f);

    float acc = 0.0f;
    const int nq = n_items >> 2;            // n_items divisible by 4 (B=4096)
    for (int i = lane; i < nq; i += 32) {
        float4 p = __ldcg(p4 + i);
        float4 n = __ldcg(n4 + i);
        acc += (n.x - p.x) / (p.x + n.x + 0.001f);
        acc += (n.y - p.y) / (p.y + n.y + 0.001f);
        acc += (n.z - p.z) / (p.z + n.z + 0.001f);
        acc += (n.w - p.w) / (p.w + n.w + 0.001f);
        p4w[i] = z4;                        // restore scratch for next replay
        n4w[i] = z4;
    }
#pragma unroll
    for (int off = 16; off > 0; off >>= 1)
        acc += __shfl_xor_sync(0xffffffffu, acc, off);
    if (lane == 0) {
        out[0] = acc;                       // single writer
        g_ctr = 0;                          // reset for next replay
    }
}

// ---------------------------------------------------------------------------
// Inputs (metadata order):
//   0: question_embeddings_pos  [2B, 1024] f32
//   1: question_embeddings_neg  [23B, 1024] f32
//   2: pos_image_embeddings     [2B, 1024] f32
//   3: neg_image_embeddings     [23B, 1024] f32
//   4: batch_size (int scalar)
// Output: f32 scalar.
// ---------------------------------------------------------------------------
extern "C" void kernel_launch(void* const* d_in, const int* in_sizes, int n_in,
                              void* d_out, int out_size) {
    const float* q_pos = (const float*)d_in[0];
    const float* q_neg = (const float*)d_in[1];
    const float* i_pos = (const float*)d_in[2];
    const float* i_neg = (const float*)d_in[3];
    float* out = (float*)d_out;

    const int D = 1024;
    const int B = in_sizes[0] / (2 * D);
    const int pos_rows = 2 * B;
    const int total_rows = 25 * B;

    // 8 x 256-thread blocks per SM = 64 warps/SM resident (full occupancy).
    int blocks = 148 * 8;
    const int max_blocks = (total_rows + 7) / 8;   // never exceed work
    if (blocks > max_blocks) blocks = max_blocks;

    contrastive_persistent_kernel<<<blocks, 256>>>(
        q_pos, i_pos, q_neg, i_neg, out, pos_rows, total_rows, B);
}

// round 13
// speedup vs baseline: 1.4294x; 1.4294x over previous
#include <cuda_runtime.h>
#include <math.h>

// Segment sums, zero-initialized at module load; finalize re-zeroes them after
// reading so every graph replay starts from zeros. Sized for B up to 8192.
__device__ float g_pos_sum[8192];
__device__ float g_neg_sum[8192];

// ---------------------------------------------------------------------------
// k1: warp-per-row exp(cosine), lane0 relaxed atomicAdd into per-item segment
//     sums (spread addresses: measured free). No barrier/fence/handshake —
//     warps retire the moment their row is done; the multi-wave launch pool
//     gives dynamic load balancing. This exact shape measured ~7.4 TB/s
//     (93% of HBM spec); every fused/persistent variant measured 20-135% worse.
//     Block 0 thread 0 zeroes out[0] for finalize's per-block atomics.
// ---------------------------------------------------------------------------
__global__ void __launch_bounds__(256) row_cos_kernel(
    const float* __restrict__ q_pos, const float* __restrict__ i_pos,
    const float* __restrict__ q_neg, const float* __restrict__ i_neg,
    float* __restrict__ out, int pos_rows, int total_rows)
{
    if (blockIdx.x == 0 && threadIdx.x == 0) out[0] = 0.0f;

    const int w = (blockIdx.x * blockDim.x + threadIdx.x) >> 5;
    const int lane = threadIdx.x & 31;
    if (w >= total_rows) return;

    const float4* __restrict__ a4;
    const float4* __restrict__ b4;
    float* __restrict__ dst;
    if (w < pos_rows) {
        a4 = reinterpret_cast<const float4*>(q_pos) + (size_t)w * 256;
        b4 = reinterpret_cast<const float4*>(i_pos) + (size_t)w * 256;
        dst = &g_pos_sum[w >> 1];                  // 2 pos rows per item
    } else {
        const int r = w - pos_rows;
        a4 = reinterpret_cast<const float4*>(q_neg) + (size_t)r * 256;
        b4 = reinterpret_cast<const float4*>(i_neg) + (size_t)r * 256;
        dst = &g_neg_sum[r / 23];                  // 23 neg rows per item
    }

    float dot = 0.0f, na2 = 0.0f, nb2 = 0.0f;
#pragma unroll
    for (int i = 0; i < 8; i++) {
        float4 va = __ldcs(a4 + lane + i * 32);    // stream-once: evict-first
        float4 vb = __ldcs(b4 + lane + i * 32);
        dot = fmaf(va.x, vb.x, dot); na2 = fmaf(va.x, va.x, na2); nb2 = fmaf(vb.x, vb.x, nb2);
        dot = fmaf(va.y, vb.y, dot); na2 = fmaf(va.y, va.y, na2); nb2 = fmaf(vb.y, vb.y, nb2);
        dot = fmaf(va.z, vb.z, dot); na2 = fmaf(va.z, va.z, na2); nb2 = fmaf(vb.z, vb.z, nb2);
        dot = fmaf(va.w, vb.w, dot); na2 = fmaf(va.w, va.w, na2); nb2 = fmaf(vb.w, vb.w, nb2);
    }
#pragma unroll
    for (int off = 16; off > 0; off >>= 1) {
        dot += __shfl_xor_sync(0xffffffffu, dot, off);
        na2 += __shfl_xor_sync(0xffffffffu, na2, off);
        nb2 += __shfl_xor_sync(0xffffffffu, nb2, off);
    }
    if (lane == 0) {
        float denom = fmaxf(sqrtf(na2) * sqrtf(nb2), 1e-8f);
        atomicAdd(dst, expf(dot / denom));         // relaxed, spread: free
    }
}

// ---------------------------------------------------------------------------
// k2: thread-per-item finalize. Reads 2*B floats (32 KB, L2-hot), computes the
//     per-item loss, re-zeroes the segment sums (replay determinism), reduces,
//     one atomicAdd per block into out[0]. Launch-floor bound (~4us)
//     regardless of grid size; all in-kernel replacements measured worse.
// ---------------------------------------------------------------------------
__global__ void __launch_bounds__(256) finalize_kernel(float* __restrict__ out, int n_items) {
    __shared__ float red[8];
    const int i = blockIdx.x * blockDim.x + threadIdx.x;

    float loss = 0.0f;
    if (i < n_items) {
        float p = __ldcg(&g_pos_sum[i]);
        float n = __ldcg(&g_neg_sum[i]);
        loss = (n - p) / (p + n + 0.001f);
        g_pos_sum[i] = 0.0f;       // restore scratch for next replay
        g_neg_sum[i] = 0.0f;
    }
#pragma unroll
    for (int off = 16; off > 0; off >>= 1)
        loss += __shfl_xor_sync(0xffffffffu, loss, off);
    if ((threadIdx.x & 31) == 0) red[threadIdx.x >> 5] = loss;
    __syncthreads();
    if (threadIdx.x == 0) {
        float acc = 0.0f;
#pragma unroll
        for (int k = 0; k < 8; k++) acc += red[k];
        atomicAdd(out, acc);
    }
}

// ---------------------------------------------------------------------------
// Inputs (metadata order):
//   0: question_embeddings_pos  [2B, 1024] f32
//   1: question_embeddings_neg  [23B, 1024] f32
//   2: pos_image_embeddings     [2B, 1024] f32
//   3: neg_image_embeddings     [23B, 1024] f32
//   4: batch_size (int scalar)
// Output: f32 scalar.
// ---------------------------------------------------------------------------
extern "C" void kernel_launch(void* const* d_in, const int* in_sizes, int n_in,
                              void* d_out, int out_size) {
    const float* q_pos = (const float*)d_in[0];
    const float* q_neg = (const float*)d_in[1];
    const float* i_pos = (const float*)d_in[2];
    const float* i_neg = (const float*)d_in[3];
    float* out = (float*)d_out;

    const int D = 1024;
    const int B = in_sizes[0] / (2 * D);
    const int pos_rows = 2 * B;
    const int total_rows = 25 * B;

    const int WPB = 8;  // 256 threads / block
    row_cos_kernel<<<(total_rows + WPB - 1) / WPB, WPB * 32>>>(
        q_pos, i_pos, q_neg, i_neg, out, pos_rows, total_rows);

    finalize_kernel<<<(B + 255) / 256, 256>>>(out, B);
}